// round 14
// baseline (speedup 1.0000x reference)
#include <cuda_runtime.h>
#include <cuda_bf16.h>
#include <stdint.h>

#define T 4096
#define D 2048
#define E 8

#define DATA  ((size_t)E * T * D)       // 64M floats (256 MB)
#define NTAG  (E * T)
#define SPLIT 1152                      // rows >= SPLIT zeroed by k_zeroA
#define LGRID 128                       // logit blocks

// ---------------- scratch ----------------
__device__ int      g_top_e[T * 2];
__device__ float    g_top_g[T * 2];
__device__ int      g_tok_row[T * 2];
__device__ int      g_loads[E];
__device__ int      g_flag[T];
__device__ unsigned g_done;            // logits completion counter (self-resetting)

// ---------------- kernel 0: routing-independent bulk zero ----------------
__global__ void __launch_bounds__(256) k_zeroA(float* __restrict__ out) {
    const int e = blockIdx.y;
    float4* o4 = (float4*)(out + ((size_t)e * T + SPLIT) * D);
    const size_t N4 = (size_t)(T - SPLIT) * D / 4;
    const float4 z = make_float4(0.f, 0.f, 0.f, 0.f);
    const int tid = threadIdx.x;
    const size_t step = (size_t)gridDim.x * 1024;
    for (size_t b = (size_t)blockIdx.x * 1024; b < N4; b += step) {
        o4[b + tid]       = z;
        o4[b + tid + 256] = z;
        o4[b + tid + 512] = z;
        o4[b + tid + 768] = z;
    }
}

// ---------------- kernel 1: pipelined fp32 logits + fused route (last block) ----------------
__global__ void __launch_bounds__(256) k_logits_route(const float* __restrict__ x,
                                                      const float* __restrict__ Wg,
                                                      float* __restrict__ out) {
    __shared__ float sW[8][1028];
    __shared__ unsigned s_rank;
    const int tid  = threadIdx.x;
    const int warp = tid >> 5;
    const int lane = tid & 31;
    const int tb = (blockIdx.x * 8 + warp) * 4;

    float a0[E], a1[E], a2[E], a3[E];
#pragma unroll
    for (int e = 0; e < E; e++) { a0[e] = 0.f; a1[e] = 0.f; a2[e] = 0.f; a3[e] = 0.f; }

    for (int c = 0; c < 2; c++) {
        __syncthreads();
        const float4* wg4 = (const float4*)(Wg + (size_t)c * 1024 * 8);
        for (int j = tid; j < 2048; j += 256) {
            float4 v = wg4[j];
            int d  = j >> 1;
            int eb = (j & 1) * 4;
            sW[eb + 0][d] = v.x; sW[eb + 1][d] = v.y;
            sW[eb + 2][d] = v.z; sW[eb + 3][d] = v.w;
        }
        __syncthreads();

        const float4* x0 = (const float4*)(x + (size_t)(tb + 0) * D + c * 1024);
        const float4* x1 = (const float4*)(x + (size_t)(tb + 1) * D + c * 1024);
        const float4* x2 = (const float4*)(x + (size_t)(tb + 2) * D + c * 1024);
        const float4* x3 = (const float4*)(x + (size_t)(tb + 3) * D + c * 1024);

        // software pipeline: prefetch next iteration's 4 loads before computing current
        float4 v0 = x0[lane], v1 = x1[lane], v2 = x2[lane], v3 = x3[lane];
#pragma unroll
        for (int i = 0; i < 8; i++) {
            const int d4 = i * 32 + lane;
            float4 n0, n1, n2, n3;
            if (i < 7) {
                const int nd = d4 + 32;
                n0 = x0[nd]; n1 = x1[nd]; n2 = x2[nd]; n3 = x3[nd];
            }
#pragma unroll
            for (int e = 0; e < E; e++) {
                float4 wv = *(const float4*)&sW[e][d4 * 4];
                a0[e] += v0.x * wv.x + v0.y * wv.y + v0.z * wv.z + v0.w * wv.w;
                a1[e] += v1.x * wv.x + v1.y * wv.y + v1.z * wv.z + v1.w * wv.w;
                a2[e] += v2.x * wv.x + v2.y * wv.y + v2.z * wv.z + v2.w * wv.w;
                a3[e] += v3.x * wv.x + v3.y * wv.y + v3.z * wv.z + v3.w * wv.w;
            }
            if (i < 7) { v0 = n0; v1 = n1; v2 = n2; v3 = n3; }
        }
    }

#pragma unroll
    for (int e = 0; e < E; e++) {
#pragma unroll
        for (int off = 16; off > 0; off >>= 1) {
            a0[e] += __shfl_down_sync(0xffffffffu, a0[e], off);
            a1[e] += __shfl_down_sync(0xffffffffu, a1[e], off);
            a2[e] += __shfl_down_sync(0xffffffffu, a2[e], off);
            a3[e] += __shfl_down_sync(0xffffffffu, a3[e], off);
        }
    }

    if (lane == 0) {
#pragma unroll
        for (int k = 0; k < 4; k++) {
            const int t = tb + k;
            float lg[E];
#pragma unroll
            for (int e = 0; e < E; e++)
                lg[e] = (k == 0) ? a0[e] : (k == 1) ? a1[e] : (k == 2) ? a2[e] : a3[e];

            float mx = lg[0];
#pragma unroll
            for (int e = 1; e < E; e++) mx = fmaxf(mx, lg[e]);
            float ex[E], sum = 0.f;
#pragma unroll
            for (int e = 0; e < E; e++) { ex[e] = __expf(lg[e] - mx); sum += ex[e]; }
            float inv = 1.0f / sum;

            int b0 = 0;
#pragma unroll
            for (int e = 1; e < E; e++) if (lg[e] > lg[b0]) b0 = e;
            int b1 = -1;
#pragma unroll
            for (int e = 0; e < E; e++) {
                if (e == b0) continue;
                if (b1 < 0 || lg[e] > lg[b1]) b1 = e;
            }
            float v3 = -1e30f;
#pragma unroll
            for (int e = 0; e < E; e++)
                if (e != b0 && e != b1) v3 = fmaxf(v3, lg[e]);

            g_top_e[t * 2 + 0] = b0;
            g_top_e[t * 2 + 1] = b1;
            g_top_g[t * 2 + 0] = ex[b0] * inv;
            g_top_g[t * 2 + 1] = ex[b1] * inv;
            g_flag[t] = (lg[b1] - v3 < 1e-3f) ? 1 : 0;
        }
    }

    // ---- last-block-done: run route with this block's 256 threads ----
    __threadfence();
    __syncthreads();
    if (tid == 0) s_rank = atomicAdd(&g_done, 1u);
    __syncthreads();
    if (s_rank != LGRID - 1) return;
    if (tid == 0) g_done = 0;           // reset for next replay
    __threadfence();                    // acquire all blocks' logits writes

    // ---- fp64 fixup for flagged tokens (256 threads) ----
    __shared__ int s_n;
    __shared__ double sred[8][8];
    __shared__ double slog[8];
    __shared__ int wsum[8];
    int* s_list = (int*)&sW[0][0];      // reuse smem (>= T ints)

    if (tid == 0) s_n = 0;
    __syncthreads();
    for (int t = tid; t < T; t += 256)
        if (g_flag[t]) { int k = atomicAdd(&s_n, 1); s_list[k] = t; }
    __syncthreads();

    for (int k = 0; k < s_n; k++) {
        const int t = s_list[k];
        double acc[E];
#pragma unroll
        for (int e = 0; e < E; e++) acc[e] = 0.0;
#pragma unroll
        for (int kk = 0; kk < 8; kk++) {
            const int d = tid + kk * 256;
            const double xv = (double)x[(size_t)t * D + d];
            const float4* w4 = (const float4*)(Wg + (size_t)d * 8);
            float4 wa = w4[0], wb = w4[1];
            acc[0] += xv * (double)wa.x; acc[1] += xv * (double)wa.y;
            acc[2] += xv * (double)wa.z; acc[3] += xv * (double)wa.w;
            acc[4] += xv * (double)wb.x; acc[5] += xv * (double)wb.y;
            acc[6] += xv * (double)wb.z; acc[7] += xv * (double)wb.w;
        }
#pragma unroll
        for (int e = 0; e < E; e++) {
#pragma unroll
            for (int off = 16; off > 0; off >>= 1)
                acc[e] += __shfl_down_sync(0xffffffffu, acc[e], off);
        }
        if (lane == 0) {
#pragma unroll
            for (int e = 0; e < E; e++) sred[warp][e] = acc[e];
        }
        __syncthreads();
        if (tid < E) {
            double s = 0.0;
#pragma unroll
            for (int w = 0; w < 8; w++) s += sred[w][tid];
            slog[tid] = s;
        }
        __syncthreads();
        if (tid == 0) {
            float lg[E];
#pragma unroll
            for (int e = 0; e < E; e++) lg[e] = (float)slog[e];
            float mx = lg[0];
#pragma unroll
            for (int e = 1; e < E; e++) mx = fmaxf(mx, lg[e]);
            float ex[E], sum = 0.f;
#pragma unroll
            for (int e = 0; e < E; e++) { ex[e] = __expf(lg[e] - mx); sum += ex[e]; }
            float inv = 1.0f / sum;
            int b0 = 0;
#pragma unroll
            for (int e = 1; e < E; e++) if (lg[e] > lg[b0]) b0 = e;
            int b1 = -1;
#pragma unroll
            for (int e = 0; e < E; e++) {
                if (e == b0) continue;
                if (b1 < 0 || lg[e] > lg[b1]) b1 = e;
            }
            g_top_e[t * 2 + 0] = b0;
            g_top_e[t * 2 + 1] = b1;
            g_top_g[t * 2 + 0] = ex[b0] * inv;
            g_top_g[t * 2 + 1] = ex[b1] * inv;
        }
        __syncthreads();
    }

    // ---- ordered per-expert compaction (256 threads, 16 tokens each) ----
    int e0[16], e1[16];
    const int t0 = tid * 16;
#pragma unroll
    for (int j = 0; j < 16; j++) {
        e0[j] = g_top_e[(t0 + j) * 2 + 0];
        e1[j] = g_top_e[(t0 + j) * 2 + 1];
    }
    __syncthreads();

    for (int e = 0; e < E; e++) {
        int cnt = 0;
#pragma unroll
        for (int j = 0; j < 16; j++) cnt += (e0[j] == e) + (e1[j] == e);

        int incl = cnt;
#pragma unroll
        for (int off = 1; off < 32; off <<= 1) {
            int v = __shfl_up_sync(0xffffffffu, incl, off);
            if (lane >= off) incl += v;
        }
        if (lane == 31) wsum[warp] = incl;
        __syncthreads();
        if (tid < 32) {
            int v = (lane < 8) ? wsum[lane] : 0;
#pragma unroll
            for (int off = 1; off < 8; off <<= 1) {
                int u = __shfl_up_sync(0xffffffffu, v, off);
                if (lane >= off) v += u;
            }
            if (lane < 8) wsum[lane] = v;
        }
        __syncthreads();

        int wbase = warp ? wsum[warp - 1] : 0;
        int p = wbase + incl - cnt;
#pragma unroll
        for (int j = 0; j < 16; j++) {
            if (e0[j] == e) {
                g_tok_row[(t0 + j) * 2 + 0] = e * T + p; p++;
            } else if (e1[j] == e) {
                g_tok_row[(t0 + j) * 2 + 1] = e * T + p; p++;
            }
        }
        if (tid == 0) {
            g_loads[e] = wsum[7];
            out[DATA + NTAG + e] = (float)wsum[7];
        }
        __syncthreads();
    }
    __threadfence();   // publish routing before kernel end (belt & braces)
}

// ---------------- kernel 3: scatter + gap-zero + tag tails ----------------
__global__ void k_fill(const float* __restrict__ x, float* __restrict__ out) {
    const int bid = blockIdx.x;
    const int i = threadIdx.x;

    if (bid >= T) {
        const int u = bid - T;
        const int e = u >> 3;
        const int s = u & 7;
        const int le = g_loads[e];
        for (int r = le + s * 256 + i; r < T; r += 8 * 256)
            out[DATA + e * T + r] = -1.0f;
        const float4 z = make_float4(0.f, 0.f, 0.f, 0.f);
        for (int r = le + s; r < SPLIT; r += 8) {
            float4* o = (float4*)(out + ((size_t)e * T + r) * D);
            o[i] = z;
            o[i + 256] = z;
        }
        return;
    }

    const int t = bid;
    const int r0 = g_tok_row[t * 2 + 0];
    const int r1 = g_tok_row[t * 2 + 1];
    const float s0 = g_top_g[t * 2 + 0];
    const float s1 = g_top_g[t * 2 + 1];

    const float4* xr = (const float4*)(x + (size_t)t * D);
    float4* o0 = (float4*)(out + (size_t)r0 * D);
    float4* o1 = (float4*)(out + (size_t)r1 * D);

    float4 a = xr[i], b = xr[i + 256];
    o0[i]       = make_float4(a.x * s0, a.y * s0, a.z * s0, a.w * s0);
    o0[i + 256] = make_float4(b.x * s0, b.y * s0, b.z * s0, b.w * s0);
    o1[i]       = make_float4(a.x * s1, a.y * s1, a.z * s1, a.w * s1);
    o1[i + 256] = make_float4(b.x * s1, b.y * s1, b.z * s1, b.w * s1);

    if (i == 0) out[DATA + r0] = (float)t;
    if (i == 1) out[DATA + r1] = (float)t;
}

// ---------------- launch ----------------
extern "C" void kernel_launch(void* const* d_in, const int* in_sizes, int n_in,
                              void* d_out, int out_size) {
    const float* x  = (const float*)d_in[0];
    const float* Wg = (const float*)d_in[1];
    float* out = (float*)d_out;

    dim3 zgrid(148, 8);
    k_zeroA<<<zgrid, 256>>>(out);
    k_logits_route<<<LGRID, 256>>>(x, Wg, out);
    k_fill<<<T + 64, 256>>>(x, out);
}

// round 15
// speedup vs baseline: 1.0667x; 1.0667x over previous
#include <cuda_runtime.h>
#include <cuda_bf16.h>
#include <stdint.h>

#define T 4096
#define D 2048
#define E 8

#define DATA  ((size_t)E * T * D)       // 64M floats (256 MB)
#define NTAG  (E * T)
#define SPLIT 1152                      // rows >= SPLIT zeroed by k_zeroA

// ---------------- scratch ----------------
__device__ int   g_top_e[T * 2];
__device__ float g_top_g[T * 2];
__device__ int   g_tok_row[T * 2];
__device__ int   g_loads[E];
__device__ int   g_flag[T];

// ---------------- kernel 0: routing-independent bulk zero ----------------
__global__ void __launch_bounds__(256) k_zeroA(float* __restrict__ out) {
    const int e = blockIdx.y;
    float4* o4 = (float4*)(out + ((size_t)e * T + SPLIT) * D);
    const size_t N4 = (size_t)(T - SPLIT) * D / 4;
    const float4 z = make_float4(0.f, 0.f, 0.f, 0.f);
    const int tid = threadIdx.x;
    const size_t step = (size_t)gridDim.x * 1024;
    for (size_t b = (size_t)blockIdx.x * 1024; b < N4; b += step) {
        o4[b + tid]       = z;
        o4[b + tid + 256] = z;
        o4[b + tid + 512] = z;
        o4[b + tid + 768] = z;
    }
}

// ---------------- kernel 1: fp32 logits, 1 token/warp, BATCHED loads ----------------
// 512 blocks x 256 threads. Per 1024-d chunk, each lane loads its 8 float4 into a
// local array BEFORE the FFMA loop -> 8 loads in flight per warp, 4096 warps
// chip-wide => DRAM-saturating x read (vs 1.6 TB/s dependency-limited before).
__global__ void __launch_bounds__(256) k_logits_f32(const float* __restrict__ x,
                                                    const float* __restrict__ Wg) {
    __shared__ float sW[8][1028];
    const int tid  = threadIdx.x;
    const int warp = tid >> 5;
    const int lane = tid & 31;
    const int t = blockIdx.x * 8 + warp;   // one token per warp

    float a[E];
#pragma unroll
    for (int e = 0; e < E; e++) a[e] = 0.f;

    for (int c = 0; c < 2; c++) {
        __syncthreads();
        const float4* wg4 = (const float4*)(Wg + (size_t)c * 1024 * 8);
        for (int j = tid; j < 2048; j += 256) {
            float4 v = wg4[j];
            int d  = j >> 1;
            int eb = (j & 1) * 4;
            sW[eb + 0][d] = v.x; sW[eb + 1][d] = v.y;
            sW[eb + 2][d] = v.z; sW[eb + 3][d] = v.w;
        }
        __syncthreads();

        const float4* xr = (const float4*)(x + (size_t)t * D + c * 1024);

        // batch ALL 8 loads first (no consumer between them -> all in flight)
        float4 xv[8];
#pragma unroll
        for (int i = 0; i < 8; i++) xv[i] = xr[i * 32 + lane];

#pragma unroll
        for (int i = 0; i < 8; i++) {
            const int d4 = i * 32 + lane;
#pragma unroll
            for (int e = 0; e < E; e++) {
                float4 wv = *(const float4*)&sW[e][d4 * 4];
                a[e] += xv[i].x * wv.x + xv[i].y * wv.y + xv[i].z * wv.z + xv[i].w * wv.w;
            }
        }
    }

#pragma unroll
    for (int e = 0; e < E; e++) {
#pragma unroll
        for (int off = 16; off > 0; off >>= 1)
            a[e] += __shfl_down_sync(0xffffffffu, a[e], off);
    }

    if (lane == 0) {
        float lg[E];
#pragma unroll
        for (int e = 0; e < E; e++) lg[e] = a[e];

        float mx = lg[0];
#pragma unroll
        for (int e = 1; e < E; e++) mx = fmaxf(mx, lg[e]);
        float ex[E], sum = 0.f;
#pragma unroll
        for (int e = 0; e < E; e++) { ex[e] = __expf(lg[e] - mx); sum += ex[e]; }
        float inv = 1.0f / sum;

        int b0 = 0;
#pragma unroll
        for (int e = 1; e < E; e++) if (lg[e] > lg[b0]) b0 = e;
        int b1 = -1;
#pragma unroll
        for (int e = 0; e < E; e++) {
            if (e == b0) continue;
            if (b1 < 0 || lg[e] > lg[b1]) b1 = e;
        }
        float v3 = -1e30f;
#pragma unroll
        for (int e = 0; e < E; e++)
            if (e != b0 && e != b1) v3 = fmaxf(v3, lg[e]);

        g_top_e[t * 2 + 0] = b0;
        g_top_e[t * 2 + 1] = b1;
        g_top_g[t * 2 + 0] = ex[b0] * inv;
        g_top_g[t * 2 + 1] = ex[b1] * inv;
        g_flag[t] = (lg[b1] - v3 < 1e-3f) ? 1 : 0;
    }
}

// ---------------- kernel 2: fp64 fixup + ordered compaction + loads ----------------
__global__ void k_route(const float* __restrict__ x, const float* __restrict__ Wg,
                        float* __restrict__ out) {
    const int NT = 512, TPB = T / NT;  // 8
    const int tid = threadIdx.x;
    const int lane = tid & 31, wid = tid >> 5;  // 16 warps
    __shared__ int wsum[16];
    __shared__ int s_list[T];
    __shared__ int s_n;
    __shared__ double sred[16][8];
    __shared__ double slog[8];

    if (tid == 0) s_n = 0;
    __syncthreads();
    for (int t = tid; t < T; t += NT)
        if (g_flag[t]) { int k = atomicAdd(&s_n, 1); s_list[k] = t; }
    __syncthreads();

    for (int k = 0; k < s_n; k++) {
        const int t = s_list[k];
        double acc[E];
#pragma unroll
        for (int e = 0; e < E; e++) acc[e] = 0.0;
#pragma unroll
        for (int kk = 0; kk < 4; kk++) {
            const int d = tid + kk * NT;
            const double xv = (double)x[(size_t)t * D + d];
            const float4* w4 = (const float4*)(Wg + (size_t)d * 8);
            float4 wa = w4[0], wb = w4[1];
            acc[0] += xv * (double)wa.x; acc[1] += xv * (double)wa.y;
            acc[2] += xv * (double)wa.z; acc[3] += xv * (double)wa.w;
            acc[4] += xv * (double)wb.x; acc[5] += xv * (double)wb.y;
            acc[6] += xv * (double)wb.z; acc[7] += xv * (double)wb.w;
        }
#pragma unroll
        for (int e = 0; e < E; e++) {
#pragma unroll
            for (int off = 16; off > 0; off >>= 1)
                acc[e] += __shfl_down_sync(0xffffffffu, acc[e], off);
        }
        if (lane == 0) {
#pragma unroll
            for (int e = 0; e < E; e++) sred[wid][e] = acc[e];
        }
        __syncthreads();
        if (tid < E) {
            double s = 0.0;
#pragma unroll
            for (int w = 0; w < 16; w++) s += sred[w][tid];
            slog[tid] = s;
        }
        __syncthreads();
        if (tid == 0) {
            float lg[E];
#pragma unroll
            for (int e = 0; e < E; e++) lg[e] = (float)slog[e];
            float mx = lg[0];
#pragma unroll
            for (int e = 1; e < E; e++) mx = fmaxf(mx, lg[e]);
            float ex[E], sum = 0.f;
#pragma unroll
            for (int e = 0; e < E; e++) { ex[e] = __expf(lg[e] - mx); sum += ex[e]; }
            float inv = 1.0f / sum;
            int b0 = 0;
#pragma unroll
            for (int e = 1; e < E; e++) if (lg[e] > lg[b0]) b0 = e;
            int b1 = -1;
#pragma unroll
            for (int e = 0; e < E; e++) {
                if (e == b0) continue;
                if (b1 < 0 || lg[e] > lg[b1]) b1 = e;
            }
            g_top_e[t * 2 + 0] = b0;
            g_top_e[t * 2 + 1] = b1;
            g_top_g[t * 2 + 0] = ex[b0] * inv;
            g_top_g[t * 2 + 1] = ex[b1] * inv;
        }
        __syncthreads();
    }

    // ---- ordered per-expert compaction ----
    int e0[TPB], e1[TPB];
    const int t0 = tid * TPB;
#pragma unroll
    for (int j = 0; j < TPB; j++) {
        e0[j] = g_top_e[(t0 + j) * 2 + 0];
        e1[j] = g_top_e[(t0 + j) * 2 + 1];
    }
    __syncthreads();

    for (int e = 0; e < E; e++) {
        int cnt = 0;
#pragma unroll
        for (int j = 0; j < TPB; j++) cnt += (e0[j] == e) + (e1[j] == e);

        int incl = cnt;
#pragma unroll
        for (int off = 1; off < 32; off <<= 1) {
            int v = __shfl_up_sync(0xffffffffu, incl, off);
            if (lane >= off) incl += v;
        }
        if (lane == 31) wsum[wid] = incl;
        __syncthreads();
        if (tid < 32) {
            int v = (tid < 16) ? wsum[tid] : 0;
#pragma unroll
            for (int off = 1; off < 16; off <<= 1) {
                int u = __shfl_up_sync(0xffffffffu, v, off);
                if (lane >= off) v += u;
            }
            if (tid < 16) wsum[tid] = v;
        }
        __syncthreads();

        int wbase = wid ? wsum[wid - 1] : 0;
        int p = wbase + incl - cnt;
#pragma unroll
        for (int j = 0; j < TPB; j++) {
            if (e0[j] == e) {
                g_tok_row[(t0 + j) * 2 + 0] = e * T + p; p++;
            } else if (e1[j] == e) {
                g_tok_row[(t0 + j) * 2 + 1] = e * T + p; p++;
            }
        }
        if (tid == 0) {
            g_loads[e] = wsum[15];
            out[DATA + NTAG + e] = (float)wsum[15];   // loads output
        }
        __syncthreads();  // before wsum reuse
    }
}

// ---------------- kernel 3: scatter + gap-zero + tag tails ----------------
__global__ void k_fill(const float* __restrict__ x, float* __restrict__ out) {
    const int bid = blockIdx.x;
    const int i = threadIdx.x;

    if (bid >= T) {
        const int u = bid - T;
        const int e = u >> 3;
        const int s = u & 7;
        const int le = g_loads[e];
        for (int r = le + s * 256 + i; r < T; r += 8 * 256)
            out[DATA + e * T + r] = -1.0f;
        const float4 z = make_float4(0.f, 0.f, 0.f, 0.f);
        for (int r = le + s; r < SPLIT; r += 8) {
            float4* o = (float4*)(out + ((size_t)e * T + r) * D);
            o[i] = z;
            o[i + 256] = z;
        }
        return;
    }

    const int t = bid;
    const int r0 = g_tok_row[t * 2 + 0];
    const int r1 = g_tok_row[t * 2 + 1];
    const float s0 = g_top_g[t * 2 + 0];
    const float s1 = g_top_g[t * 2 + 1];

    const float4* xr = (const float4*)(x + (size_t)t * D);
    float4* o0 = (float4*)(out + (size_t)r0 * D);
    float4* o1 = (float4*)(out + (size_t)r1 * D);

    float4 a = xr[i], b = xr[i + 256];
    o0[i]       = make_float4(a.x * s0, a.y * s0, a.z * s0, a.w * s0);
    o0[i + 256] = make_float4(b.x * s0, b.y * s0, b.z * s0, b.w * s0);
    o1[i]       = make_float4(a.x * s1, a.y * s1, a.z * s1, a.w * s1);
    o1[i + 256] = make_float4(b.x * s1, b.y * s1, b.z * s1, b.w * s1);

    if (i == 0) out[DATA + r0] = (float)t;
    if (i == 1) out[DATA + r1] = (float)t;
}

// ---------------- launch ----------------
extern "C" void kernel_launch(void* const* d_in, const int* in_sizes, int n_in,
                              void* d_out, int out_size) {
    const float* x  = (const float*)d_in[0];
    const float* Wg = (const float*)d_in[1];
    float* out = (float*)d_out;

    dim3 zgrid(148, 8);
    k_zeroA<<<zgrid, 256>>>(out);
    k_logits_f32<<<512, 256>>>(x, Wg);
    k_route<<<1, 512>>>(x, Wg, out);
    k_fill<<<T + 64, 256>>>(x, out);
}

// round 16
// speedup vs baseline: 1.0884x; 1.0204x over previous
#include <cuda_runtime.h>
#include <cuda_bf16.h>
#include <stdint.h>

#define T 4096
#define D 2048
#define E 8

#define DATA  ((size_t)E * T * D)       // 64M floats (256 MB)
#define NTAG  (E * T)
#define SPLIT 1152                      // rows >= SPLIT zeroed by k_zeroA

// ---------------- scratch ----------------
__device__ int   g_top_e[T * 2];
__device__ float g_top_g[T * 2];
__device__ int   g_tok_row[T * 2];
__device__ int   g_loads[E];
__device__ int   g_flag[T];

// lazily created on first (uncaptured correctness) call
static cudaStream_t g_s1 = nullptr, g_s2 = nullptr;
static cudaEvent_t  g_e0 = nullptr, g_e1 = nullptr, g_e2 = nullptr;
static int g_tried = 0;

// ---------------- kernel 0: routing-independent bulk zero ----------------
__global__ void __launch_bounds__(256) k_zeroA(float* __restrict__ out) {
    const int e = blockIdx.y;
    float4* o4 = (float4*)(out + ((size_t)e * T + SPLIT) * D);
    const size_t N4 = (size_t)(T - SPLIT) * D / 4;
    const float4 z = make_float4(0.f, 0.f, 0.f, 0.f);
    const int tid = threadIdx.x;
    const size_t step = (size_t)gridDim.x * 1024;
    for (size_t b = (size_t)blockIdx.x * 1024; b < N4; b += step) {
        o4[b + tid]       = z;
        o4[b + tid + 256] = z;
        o4[b + tid + 512] = z;
        o4[b + tid + 768] = z;
    }
}

// ---------------- kernel 1: fp32 logits, 1 token/warp, batched loads ----------------
__global__ void __launch_bounds__(256) k_logits_f32(const float* __restrict__ x,
                                                    const float* __restrict__ Wg) {
    __shared__ float sW[8][1028];
    const int tid  = threadIdx.x;
    const int warp = tid >> 5;
    const int lane = tid & 31;
    const int t = blockIdx.x * 8 + warp;

    float a[E];
#pragma unroll
    for (int e = 0; e < E; e++) a[e] = 0.f;

    for (int c = 0; c < 2; c++) {
        __syncthreads();
        const float4* wg4 = (const float4*)(Wg + (size_t)c * 1024 * 8);
        for (int j = tid; j < 2048; j += 256) {
            float4 v = wg4[j];
            int d  = j >> 1;
            int eb = (j & 1) * 4;
            sW[eb + 0][d] = v.x; sW[eb + 1][d] = v.y;
            sW[eb + 2][d] = v.z; sW[eb + 3][d] = v.w;
        }
        __syncthreads();

        const float4* xr = (const float4*)(x + (size_t)t * D + c * 1024);

        float4 xv[8];
#pragma unroll
        for (int i = 0; i < 8; i++) xv[i] = xr[i * 32 + lane];

#pragma unroll
        for (int i = 0; i < 8; i++) {
            const int d4 = i * 32 + lane;
#pragma unroll
            for (int e = 0; e < E; e++) {
                float4 wv = *(const float4*)&sW[e][d4 * 4];
                a[e] += xv[i].x * wv.x + xv[i].y * wv.y + xv[i].z * wv.z + xv[i].w * wv.w;
            }
        }
    }

#pragma unroll
    for (int e = 0; e < E; e++) {
#pragma unroll
        for (int off = 16; off > 0; off >>= 1)
            a[e] += __shfl_down_sync(0xffffffffu, a[e], off);
    }

    if (lane == 0) {
        float lg[E];
#pragma unroll
        for (int e = 0; e < E; e++) lg[e] = a[e];

        float mx = lg[0];
#pragma unroll
        for (int e = 1; e < E; e++) mx = fmaxf(mx, lg[e]);
        float ex[E], sum = 0.f;
#pragma unroll
        for (int e = 0; e < E; e++) { ex[e] = __expf(lg[e] - mx); sum += ex[e]; }
        float inv = 1.0f / sum;

        int b0 = 0;
#pragma unroll
        for (int e = 1; e < E; e++) if (lg[e] > lg[b0]) b0 = e;
        int b1 = -1;
#pragma unroll
        for (int e = 0; e < E; e++) {
            if (e == b0) continue;
            if (b1 < 0 || lg[e] > lg[b1]) b1 = e;
        }
        float v3 = -1e30f;
#pragma unroll
        for (int e = 0; e < E; e++)
            if (e != b0 && e != b1) v3 = fmaxf(v3, lg[e]);

        g_top_e[t * 2 + 0] = b0;
        g_top_e[t * 2 + 1] = b1;
        g_top_g[t * 2 + 0] = ex[b0] * inv;
        g_top_g[t * 2 + 1] = ex[b1] * inv;
        g_flag[t] = (lg[b1] - v3 < 1e-3f) ? 1 : 0;
    }
}

// ---------------- kernel 2: fp64 fixup + ordered compaction + loads ----------------
__global__ void k_route(const float* __restrict__ x, const float* __restrict__ Wg,
                        float* __restrict__ out) {
    const int NT = 512, TPB = T / NT;  // 8
    const int tid = threadIdx.x;
    const int lane = tid & 31, wid = tid >> 5;  // 16 warps
    __shared__ int wsum[16];
    __shared__ int s_list[T];
    __shared__ int s_n;
    __shared__ double sred[16][8];
    __shared__ double slog[8];

    if (tid == 0) s_n = 0;
    __syncthreads();
    for (int t = tid; t < T; t += NT)
        if (g_flag[t]) { int k = atomicAdd(&s_n, 1); s_list[k] = t; }
    __syncthreads();

    for (int k = 0; k < s_n; k++) {
        const int t = s_list[k];
        double acc[E];
#pragma unroll
        for (int e = 0; e < E; e++) acc[e] = 0.0;
#pragma unroll
        for (int kk = 0; kk < 4; kk++) {
            const int d = tid + kk * NT;
            const double xv = (double)x[(size_t)t * D + d];
            const float4* w4 = (const float4*)(Wg + (size_t)d * 8);
            float4 wa = w4[0], wb = w4[1];
            acc[0] += xv * (double)wa.x; acc[1] += xv * (double)wa.y;
            acc[2] += xv * (double)wa.z; acc[3] += xv * (double)wa.w;
            acc[4] += xv * (double)wb.x; acc[5] += xv * (double)wb.y;
            acc[6] += xv * (double)wb.z; acc[7] += xv * (double)wb.w;
        }
#pragma unroll
        for (int e = 0; e < E; e++) {
#pragma unroll
            for (int off = 16; off > 0; off >>= 1)
                acc[e] += __shfl_down_sync(0xffffffffu, acc[e], off);
        }
        if (lane == 0) {
#pragma unroll
            for (int e = 0; e < E; e++) sred[wid][e] = acc[e];
        }
        __syncthreads();
        if (tid < E) {
            double s = 0.0;
#pragma unroll
            for (int w = 0; w < 16; w++) s += sred[w][tid];
            slog[tid] = s;
        }
        __syncthreads();
        if (tid == 0) {
            float lg[E];
#pragma unroll
            for (int e = 0; e < E; e++) lg[e] = (float)slog[e];
            float mx = lg[0];
#pragma unroll
            for (int e = 1; e < E; e++) mx = fmaxf(mx, lg[e]);
            float ex[E], sum = 0.f;
#pragma unroll
            for (int e = 0; e < E; e++) { ex[e] = __expf(lg[e] - mx); sum += ex[e]; }
            float inv = 1.0f / sum;
            int b0 = 0;
#pragma unroll
            for (int e = 1; e < E; e++) if (lg[e] > lg[b0]) b0 = e;
            int b1 = -1;
#pragma unroll
            for (int e = 0; e < E; e++) {
                if (e == b0) continue;
                if (b1 < 0 || lg[e] > lg[b1]) b1 = e;
            }
            g_top_e[t * 2 + 0] = b0;
            g_top_e[t * 2 + 1] = b1;
            g_top_g[t * 2 + 0] = ex[b0] * inv;
            g_top_g[t * 2 + 1] = ex[b1] * inv;
        }
        __syncthreads();
    }

    // ---- ordered per-expert compaction ----
    int e0[TPB], e1[TPB];
    const int t0 = tid * TPB;
#pragma unroll
    for (int j = 0; j < TPB; j++) {
        e0[j] = g_top_e[(t0 + j) * 2 + 0];
        e1[j] = g_top_e[(t0 + j) * 2 + 1];
    }
    __syncthreads();

    for (int e = 0; e < E; e++) {
        int cnt = 0;
#pragma unroll
        for (int j = 0; j < TPB; j++) cnt += (e0[j] == e) + (e1[j] == e);

        int incl = cnt;
#pragma unroll
        for (int off = 1; off < 32; off <<= 1) {
            int v = __shfl_up_sync(0xffffffffu, incl, off);
            if (lane >= off) incl += v;
        }
        if (lane == 31) wsum[wid] = incl;
        __syncthreads();
        if (tid < 32) {
            int v = (tid < 16) ? wsum[tid] : 0;
#pragma unroll
            for (int off = 1; off < 16; off <<= 1) {
                int u = __shfl_up_sync(0xffffffffu, v, off);
                if (lane >= off) v += u;
            }
            if (tid < 16) wsum[tid] = v;
        }
        __syncthreads();

        int wbase = wid ? wsum[wid - 1] : 0;
        int p = wbase + incl - cnt;
#pragma unroll
        for (int j = 0; j < TPB; j++) {
            if (e0[j] == e) {
                g_tok_row[(t0 + j) * 2 + 0] = e * T + p; p++;
            } else if (e1[j] == e) {
                g_tok_row[(t0 + j) * 2 + 1] = e * T + p; p++;
            }
        }
        if (tid == 0) {
            g_loads[e] = wsum[15];
            out[DATA + NTAG + e] = (float)wsum[15];
        }
        __syncthreads();
    }
}

// ---------------- kernel 3: scatter + gap-zero + tag tails ----------------
__global__ void k_fill(const float* __restrict__ x, float* __restrict__ out) {
    const int bid = blockIdx.x;
    const int i = threadIdx.x;

    if (bid >= T) {
        const int u = bid - T;
        const int e = u >> 3;
        const int s = u & 7;
        const int le = g_loads[e];
        for (int r = le + s * 256 + i; r < T; r += 8 * 256)
            out[DATA + e * T + r] = -1.0f;
        const float4 z = make_float4(0.f, 0.f, 0.f, 0.f);
        for (int r = le + s; r < SPLIT; r += 8) {
            float4* o = (float4*)(out + ((size_t)e * T + r) * D);
            o[i] = z;
            o[i + 256] = z;
        }
        return;
    }

    const int t = bid;
    const int r0 = g_tok_row[t * 2 + 0];
    const int r1 = g_tok_row[t * 2 + 1];
    const float s0 = g_top_g[t * 2 + 0];
    const float s1 = g_top_g[t * 2 + 1];

    const float4* xr = (const float4*)(x + (size_t)t * D);
    float4* o0 = (float4*)(out + (size_t)r0 * D);
    float4* o1 = (float4*)(out + (size_t)r1 * D);

    float4 a = xr[i], b = xr[i + 256];
    o0[i]       = make_float4(a.x * s0, a.y * s0, a.z * s0, a.w * s0);
    o0[i + 256] = make_float4(b.x * s0, b.y * s0, b.z * s0, b.w * s0);
    o1[i]       = make_float4(a.x * s1, a.y * s1, a.z * s1, a.w * s1);
    o1[i + 256] = make_float4(b.x * s1, b.y * s1, b.z * s1, b.w * s1);

    if (i == 0) out[DATA + r0] = (float)t;
    if (i == 1) out[DATA + r1] = (float)t;
}

// ---------------- launch: TRUE fork/join — no mid-pipeline work on legacy stream ----------------
extern "C" void kernel_launch(void* const* d_in, const int* in_sizes, int n_in,
                              void* d_out, int out_size) {
    const float* x  = (const float*)d_in[0];
    const float* Wg = (const float*)d_in[1];
    float* out = (float*)d_out;

    if (!g_tried) {
        g_tried = 1;
        if (cudaStreamCreateWithFlags(&g_s1, cudaStreamNonBlocking) != cudaSuccess) g_s1 = nullptr;
        if (cudaStreamCreateWithFlags(&g_s2, cudaStreamNonBlocking) != cudaSuccess) g_s2 = nullptr;
        if (cudaEventCreateWithFlags(&g_e0, cudaEventDisableTiming) != cudaSuccess) g_e0 = nullptr;
        if (cudaEventCreateWithFlags(&g_e1, cudaEventDisableTiming) != cudaSuccess) g_e1 = nullptr;
        if (cudaEventCreateWithFlags(&g_e2, cudaEventDisableTiming) != cudaSuccess) g_e2 = nullptr;
    }

    dim3 zgrid(148, 8);

    if (g_s1 && g_s2 && g_e0 && g_e1 && g_e2) {
        // anchor on legacy stream, then fork onto non-blocking streams
        cudaEventRecord(g_e0, 0);
        cudaStreamWaitEvent(g_s1, g_e0, 0);
        cudaStreamWaitEvent(g_s2, g_e0, 0);

        // branch A (s2): bulk zero — independent of routing
        k_zeroA<<<zgrid, 256, 0, g_s2>>>(out);

        // branch B (s1): logits -> route
        k_logits_f32<<<512, 256, 0, g_s1>>>(x, Wg);
        k_route<<<1, 512, 0, g_s1>>>(x, Wg, out);

        // join back to legacy stream, final fill
        cudaEventRecord(g_e1, g_s1);
        cudaEventRecord(g_e2, g_s2);
        cudaStreamWaitEvent(0, g_e1, 0);
        cudaStreamWaitEvent(0, g_e2, 0);
        k_fill<<<T + 64, 256>>>(x, out);
    } else {
        // serial fallback (== round-15 structure)
        k_zeroA<<<zgrid, 256>>>(out);
        k_logits_f32<<<512, 256>>>(x, Wg);
        k_route<<<1, 512>>>(x, Wg, out);
        k_fill<<<T + 64, 256>>>(x, out);
    }
}